// round 13
// baseline (speedup 1.0000x reference)
#include <cuda_runtime.h>
#include <cuda_fp16.h>
#include <math.h>

// Scratch: per-node projections P[n][0:16] = z[n]@W1_top, P[n][16:32] = z[n]@W1_bot,
// plus an fp16 shadow copy of z for the adj_logits dot.
#define MAX_NODES (131072)
__device__ __align__(256) float  g_P [(size_t)MAX_NODES * 32];
__device__ __align__(256) __half g_zh[(size_t)MAX_NODES * 128];

__device__ int g_ei_is64;

// Packed fp32x2 FMA (bit-exact vs two scalar FMAs)
__device__ __forceinline__ void ffma2(unsigned long long& d,
                                      unsigned long long a,
                                      unsigned long long b)
{
    asm("fma.rn.f32x2 %0, %1, %2, %0;" : "+l"(d) : "l"(a), "l"(b));
}
__device__ __forceinline__ unsigned long long pk2(float v)
{
    unsigned long long r;
    asm("mov.b64 %0, {%1, %1};" : "=l"(r) : "f"(v));
    return r;
}

// ---------------------------------------------------------------------------
// Kernel 1: projection.  256 threads/block, 1 node/thread (256 nodes/block).
// Same 36KB smem as before but 2x the warps per SM (1536 threads) -> more
// outstanding DRAM loads; this kernel is HBM-streaming-bound (~90MB).
// z staged through smem in 16-float K-chunks with register prefetch of the
// next chunk; fp16 shadow emitted during staging; P written back through
// smem (two passes) so stores coalesce.
// ---------------------------------------------------------------------------
#define PBLK 256
#define NPB  256
#define TS2  20    // tile words/row (16 data + 4 pad; 80 B rows, 16B-aligned)

__global__ __launch_bounds__(PBLK)
void proj_kernel(const float* __restrict__ z,
                 const float* __restrict__ W1,   // [256,16] row-major
                 const long long* __restrict__ ei_as64,
                 int N, int E)
{
    __shared__ __align__(16) float sW1[256 * 16];     // 16 KB
    __shared__ __align__(16) float tile[NPB * TS2];   // 20 KB

    // stage W1 (coalesced float4)
    {
        const float4* w4 = reinterpret_cast<const float4*>(W1);
        float4* s4 = reinterpret_cast<float4*>(sW1);
        for (int j = threadIdx.x; j < 1024; j += PBLK)
            s4[j] = w4[j];
    }

    // edge dtype detect (block 0, warp 0); see prior-round rationale.
    if (blockIdx.x == 0 && threadIdx.x < 32) {
        int cnt = E < 32 ? E : 32;
        bool ok = true;
        if ((int)threadIdx.x < cnt) {
            long long v = ei_as64[threadIdx.x];
            ok = (v >= 0 && v < (long long)N);
        }
        unsigned m = __ballot_sync(0xffffffffu, ok);
        if (threadIdx.x == 0) g_ei_is64 = (m == 0xffffffffu) ? 1 : 0;
    }

    const int tid  = threadIdx.x;
    const int base = blockIdx.x * NPB;
    const float4* z4 = reinterpret_cast<const float4*>(z);

    // staging slice mapping: element j (0..3) -> row r=g>>2, col c4=g&3
    int rr[4], cc[4], grN[4];
    size_t gidx[4];
#pragma unroll
    for (int j = 0; j < 4; j++) {
        int g  = tid + j * PBLK;
        rr[j]  = g >> 2;
        cc[j]  = g & 3;
        int gr = base + rr[j];
        grN[j] = gr;
        int grc = gr < N ? gr : (N - 1);
        gidx[j] = (size_t)grc * 32 + cc[j];
    }

    unsigned long long accT2[8], accB2[8];
#pragma unroll
    for (int j = 0; j < 8; j++) { accT2[j] = 0ull; accB2[j] = 0ull; }

    // prefetch chunk 0
    float4 pre[4];
#pragma unroll
    for (int j = 0; j < 4; j++) pre[j] = z4[gidx[j]];

#pragma unroll
    for (int c = 0; c < 8; c++) {           // 8 chunks x 16 K-floats
        __syncthreads();
#pragma unroll
        for (int j = 0; j < 4; j++) {
            float4 v = pre[j];
            *reinterpret_cast<float4*>(&tile[rr[j] * TS2 + cc[j] * 4]) = v;
            if (grN[j] < N) {
                __half2 hlo = __floats2half2_rn(v.x, v.y);
                __half2 hhi = __floats2half2_rn(v.z, v.w);
                uint2 hp;
                hp.x = *reinterpret_cast<unsigned*>(&hlo);
                hp.y = *reinterpret_cast<unsigned*>(&hhi);
                *reinterpret_cast<uint2*>(
                    reinterpret_cast<char*>(g_zh) + (size_t)grN[j] * 256 + c * 32 + cc[j] * 8) = hp;
            }
        }
        if (c < 7) {
#pragma unroll
            for (int j = 0; j < 4; j++) pre[j] = z4[gidx[j] + (c + 1) * 4];
        }
        __syncthreads();
#pragma unroll
        for (int i = 0; i < 4; i++) {
            float4 zz = *reinterpret_cast<const float4*>(&tile[tid * TS2 + i * 4]);
            float zv[4] = { zz.x, zz.y, zz.z, zz.w };
#pragma unroll
            for (int k = 0; k < 4; k++) {
                int d = c * 16 + i * 4 + k;
                unsigned long long zp = pk2(zv[k]);
                const ulonglong2* wt = reinterpret_cast<const ulonglong2*>(&sW1[d * 16]);
                const ulonglong2* wb = reinterpret_cast<const ulonglong2*>(&sW1[(128 + d) * 16]);
#pragma unroll
                for (int q = 0; q < 4; q++) {
                    ulonglong2 pt = wt[q];
                    ulonglong2 pb = wb[q];
                    ffma2(accT2[q*2+0], zp, pt.x); ffma2(accT2[q*2+1], zp, pt.y);
                    ffma2(accB2[q*2+0], zp, pb.x); ffma2(accB2[q*2+1], zp, pb.y);
                }
            }
        }
    }

    // P writeback via smem, two passes (top 16, bottom 16), coalesced stores
    float4* gP4 = reinterpret_cast<float4*>(g_P);

    __syncthreads();
#pragma unroll
    for (int q = 0; q < 4; q++) {
        ulonglong2 t; t.x = accT2[q*2]; t.y = accT2[q*2+1];
        *reinterpret_cast<ulonglong2*>(&tile[tid * TS2 + q * 4]) = t;
    }
    __syncthreads();
#pragma unroll
    for (int j = 0; j < 4; j++)
        if (grN[j] < N)
            gP4[(size_t)grN[j] * 8 + cc[j]] =
                *reinterpret_cast<const float4*>(&tile[rr[j] * TS2 + cc[j] * 4]);

    __syncthreads();
#pragma unroll
    for (int q = 0; q < 4; q++) {
        ulonglong2 b; b.x = accB2[q*2]; b.y = accB2[q*2+1];
        *reinterpret_cast<ulonglong2*>(&tile[tid * TS2 + q * 4]) = b;
    }
    __syncthreads();
#pragma unroll
    for (int j = 0; j < 4; j++)
        if (grN[j] < N)
            gP4[(size_t)grN[j] * 8 + 4 + cc[j]] =
                *reinterpret_cast<const float4*>(&tile[rr[j] * TS2 + cc[j] * 4]);
}

// ---------------------------------------------------------------------------
// fp16 chained dot of 8 elements: 1 HMUL2 + 3 HFMA2 (each half-lane sums only
// 4 products), then 1 cvt-pair + add into fp32.
// ---------------------------------------------------------------------------
__device__ __forceinline__ float dot8_h(uint4 a, uint4 b)
{
    __half2 s = __hmul2(*reinterpret_cast<const __half2*>(&a.x),
                        *reinterpret_cast<const __half2*>(&b.x));
    s = __hfma2(*reinterpret_cast<const __half2*>(&a.y),
                *reinterpret_cast<const __half2*>(&b.y), s);
    s = __hfma2(*reinterpret_cast<const __half2*>(&a.z),
                *reinterpret_cast<const __half2*>(&b.z), s);
    s = __hfma2(*reinterpret_cast<const __half2*>(&a.w),
                *reinterpret_cast<const __half2*>(&b.w), s);
    float2 f = __half22float2(s);
    return f.x + f.y;
}

// ---------------------------------------------------------------------------
// Kernel 2: per-edge work, 8 lanes per edge, 32-bit byte-offset addressing
// (avoids 64-bit IMAD.WIDE index chains).
// out layout: [adj_logits (E), weights (E)]
// ---------------------------------------------------------------------------
__global__ __launch_bounds__(256)
void edge_kernel(const void* __restrict__ ei_raw,   // [2,E] int64 OR int32
                 const float* __restrict__ b1,
                 const float* __restrict__ W2,
                 const float* __restrict__ b2,
                 float* __restrict__ out,
                 int E, int N)
{
    int t   = blockIdx.x * blockDim.x + threadIdx.x;
    int e   = t >> 3;
    int sub = t & 7;
    bool valid = (e < E);
    int ec = valid ? e : (E - 1);

    int row, col;
    if (g_ei_is64) {
        const long long* ei = (const long long*)ei_raw;
        row = (int)ei[ec];
        col = (int)ei[(size_t)E + ec];
    } else {
        const int* ei = (const int*)ei_raw;
        row = ei[ec];
        col = ei[(size_t)E + ec];
    }
    row = min(max(row, 0), N - 1);
    col = min(max(col, 0), N - 1);

    // 32-bit byte offsets: zh row = 256 B, P row = 128 B
    const char* zh = reinterpret_cast<const char*>(g_zh);
    const char* Pb = reinterpret_cast<const char*>(g_P);
    unsigned zr_off = ((unsigned)row << 8) + ((unsigned)sub << 4);
    unsigned zc_off = ((unsigned)col << 8) + ((unsigned)sub << 4);

    uint4 a0  = *reinterpret_cast<const uint4*>(zh + zr_off);
    uint4 b0  = *reinterpret_cast<const uint4*>(zh + zc_off);
    uint4 a1  = *reinterpret_cast<const uint4*>(zh + zr_off + 128);
    uint4 b1u = *reinterpret_cast<const uint4*>(zh + zc_off + 128);
    float acc = dot8_h(a0, b0) + dot8_h(a1, b1u);

    acc += __shfl_xor_sync(0xffffffffu, acc, 1);
    acc += __shfl_xor_sync(0xffffffffu, acc, 2);
    acc += __shfl_xor_sync(0xffffffffu, acc, 4);

    // MLP: each lane covers 2 hidden units
    float2 pr = *reinterpret_cast<const float2*>(Pb + ((unsigned)row << 7) + ((unsigned)sub << 3));
    float2 pc = *reinterpret_cast<const float2*>(Pb + ((unsigned)col << 7) + 64u + ((unsigned)sub << 3));
    float2 bb = reinterpret_cast<const float2*>(b1)[sub];
    float2 w2 = reinterpret_cast<const float2*>(W2)[sub];

    float h0 = fmaxf(pr.x + pc.x + bb.x, 0.f);
    float h1 = fmaxf(pr.y + pc.y + bb.y, 0.f);

    float part = h0 * w2.x + h1 * w2.y;
    part += __shfl_xor_sync(0xffffffffu, part, 1);
    part += __shfl_xor_sync(0xffffffffu, part, 2);
    part += __shfl_xor_sync(0xffffffffu, part, 4);

    if (valid && sub == 0) {
        float x = part + b2[0];
        float w = fmaxf(x, 0.f) + log1pf(expf(-fabsf(x)));
        out[e]             = acc;
        out[(size_t)E + e] = w;
    }
}

// ---------------------------------------------------------------------------
// Launch
// ---------------------------------------------------------------------------
extern "C" void kernel_launch(void* const* d_in, const int* in_sizes, int n_in,
                              void* d_out, int out_size)
{
    const float* z  = (const float*)d_in[0];        // [N,128] f32
    const void*  ei = d_in[1];                      // [2,E]   i64 or i32
    const float* W1 = (const float*)d_in[2];        // [256,16] f32
    const float* b1 = (const float*)d_in[3];        // [16]
    const float* W2 = (const float*)d_in[4];        // [16,1]
    const float* b2 = (const float*)d_in[5];        // [1]
    float*       out = (float*)d_out;

    int N = in_sizes[0] / 128;
    int E = in_sizes[1] / 2;

    int blocks1 = (N + NPB - 1) / NPB;
    proj_kernel<<<blocks1, PBLK>>>(z, W1, (const long long*)ei, N, E);

    long long threads2 = (long long)E * 8;
    int blocks2 = (int)((threads2 + 255) / 256);
    edge_kernel<<<blocks2, 256>>>(ei, b1, W2, b2, out, E, N);
}